// round 6
// baseline (speedup 1.0000x reference)
#include <cuda_runtime.h>
#include <math.h>

#define D_MODEL 1024
#define LSEQ    2048
#define NTOK    8192          // B * L
#define NHEAD   16
#define HDIM    64
#define FFH     2048

// ---------------- packed f32x2 helpers (Blackwell dual-FMA pipe) ----------------
typedef unsigned long long u64;
__device__ __forceinline__ u64 pack2(float lo, float hi) {
    u64 d; asm("mov.b64 %0, {%1, %2};" : "=l"(d) : "f"(lo), "f"(hi)); return d;
}
__device__ __forceinline__ float2 unpack2(u64 v) {
    float2 r; asm("mov.b64 {%0, %1}, %2;" : "=f"(r.x), "=f"(r.y) : "l"(v)); return r;
}
__device__ __forceinline__ void ffma2(u64& d, u64 a, u64 b) {
    asm("fma.rn.f32x2 %0, %1, %2, %0;" : "+l"(d) : "l"(a), "l"(b));
}
__device__ __forceinline__ u64 mul2(u64 a, u64 b) {
    u64 d; asm("mul.rn.f32x2 %0, %1, %2;" : "=l"(d) : "l"(a), "l"(b)); return d;
}

// ---------------- scratch (allocation-free: __device__ globals) ----------------
__device__ float g_h  [NTOK * D_MODEL];       // LN output (reused for both LNs)
__device__ float g_qkv[NTOK * 3 * D_MODEL];   // QKV projection
__device__ float g_ctx[NTOK * D_MODEL];       // attention context
__device__ float g_x1 [NTOK * D_MODEL];       // post-attention residual
__device__ float g_ff [NTOK * FFH];           // FF1 output (post-GELU)

// ---------------- LayerNorm ----------------
__global__ __launch_bounds__(256) void ln_kernel(const float* __restrict__ x,
                                                 const float* __restrict__ g,
                                                 const float* __restrict__ b,
                                                 float* __restrict__ out) {
    int row = blockIdx.x;
    int t = threadIdx.x;                    // 256 threads, 4 floats each
    const float4* xr = (const float4*)(x + (size_t)row * D_MODEL);
    float4 v = xr[t];
    float s  = v.x + v.y + v.z + v.w;
    float ss = v.x*v.x + v.y*v.y + v.z*v.z + v.w*v.w;
    #pragma unroll
    for (int o = 16; o > 0; o >>= 1) {
        s  += __shfl_xor_sync(0xffffffffu, s,  o);
        ss += __shfl_xor_sync(0xffffffffu, ss, o);
    }
    __shared__ float ssum[8], ssq[8];
    __shared__ float stats[2];
    int warp = t >> 5, lane = t & 31;
    if (lane == 0) { ssum[warp] = s; ssq[warp] = ss; }
    __syncthreads();
    if (t == 0) {
        float S = 0.f, SS = 0.f;
        #pragma unroll
        for (int i = 0; i < 8; i++) { S += ssum[i]; SS += ssq[i]; }
        float mu  = S * (1.0f / D_MODEL);
        float var = SS * (1.0f / D_MODEL) - mu * mu;
        stats[0] = mu;
        stats[1] = rsqrtf(var + 1e-5f);
    }
    __syncthreads();
    float mu = stats[0], rstd = stats[1];
    float4 gg = ((const float4*)g)[t];
    float4 bb = ((const float4*)b)[t];
    float4 o;
    o.x = (v.x - mu) * rstd * gg.x + bb.x;
    o.y = (v.y - mu) * rstd * gg.y + bb.y;
    o.z = (v.z - mu) * rstd * gg.z + bb.z;
    o.w = (v.w - mu) * rstd * gg.w + bb.w;
    ((float4*)(out + (size_t)row * D_MODEL))[t] = o;
}

// ---------------- SGEMM: C[M,N] = A[M,K] @ W[K,N] + bias (+gelu|+res) ----------
// BM=BN=128, BK=8, 256 threads, 8x8 microtile, FFMA2 inner loop.
// EPI: 0 = bias, 1 = bias + exact GELU, 2 = bias + residual
template<int EPI>
__global__ __launch_bounds__(256) void sgemm(int M, int N, int K,
                                             const float* __restrict__ A,
                                             const float* __restrict__ W,
                                             const float* __restrict__ bias,
                                             const float* __restrict__ res,
                                             float* __restrict__ C) {
    __shared__ float As[8][128];
    __shared__ float Bs[8][128];
    int bm = blockIdx.y * 128;
    int bn = blockIdx.x * 128;
    int tid  = threadIdx.x;
    int trow = tid >> 4;          // 0..15
    int tcol = tid & 15;          // 0..15

    int aRow = tid >> 1;          // 0..127
    int aK   = (tid & 1) * 4;     // 0 or 4
    int bRow = tid >> 5;          // 0..7
    int bCol = (tid & 31) * 4;    // 0..124

    const float* Aptr = A + (size_t)(bm + aRow) * K + aK;
    const float* Wptr = W + (size_t)bRow * N + bn + bCol;

    // accumulator: 8 rows x 4 column-pairs of packed f32x2
    u64 acc2[8][4] = {};

    for (int k0 = 0; k0 < K; k0 += 8) {
        float4 av = *(const float4*)(Aptr + k0);
        float4 bv = *(const float4*)(Wptr + (size_t)k0 * N);
        As[aK + 0][aRow] = av.x;
        As[aK + 1][aRow] = av.y;
        As[aK + 2][aRow] = av.z;
        As[aK + 3][aRow] = av.w;
        *(float4*)&Bs[bRow][bCol] = bv;
        __syncthreads();
        #pragma unroll
        for (int kk = 0; kk < 8; kk++) {
            float ra[8];
            *(float4*)(ra)     = *(const float4*)&As[kk][trow * 8];
            *(float4*)(ra + 4) = *(const float4*)&As[kk][trow * 8 + 4];
            // B fragment: two 16B quads -> four packed f32x2 (register pairs)
            const u64* bp0 = (const u64*)&Bs[kk][tcol * 8];
            u64 rb2[4];
            rb2[0] = bp0[0]; rb2[1] = bp0[1]; rb2[2] = bp0[2]; rb2[3] = bp0[3];
            #pragma unroll
            for (int i = 0; i < 8; i++) {
                u64 a2 = pack2(ra[i], ra[i]);
                #pragma unroll
                for (int j = 0; j < 4; j++) ffma2(acc2[i][j], a2, rb2[j]);
            }
        }
        __syncthreads();
    }

    #pragma unroll
    for (int i = 0; i < 8; i++) {
        int row = bm + trow * 8 + i;
        #pragma unroll
        for (int j4 = 0; j4 < 2; j4++) {
            int col = bn + tcol * 8 + j4 * 4;
            float4 bs = *(const float4*)&bias[col];
            float2 p0 = unpack2(acc2[i][j4 * 2 + 0]);
            float2 p1 = unpack2(acc2[i][j4 * 2 + 1]);
            float v0 = p0.x + bs.x;
            float v1 = p0.y + bs.y;
            float v2 = p1.x + bs.z;
            float v3 = p1.y + bs.w;
            if (EPI == 1) {  // exact GELU
                v0 = 0.5f * v0 * (1.0f + erff(v0 * 0.70710678118654752f));
                v1 = 0.5f * v1 * (1.0f + erff(v1 * 0.70710678118654752f));
                v2 = 0.5f * v2 * (1.0f + erff(v2 * 0.70710678118654752f));
                v3 = 0.5f * v3 * (1.0f + erff(v3 * 0.70710678118654752f));
            }
            if (EPI == 2) {  // residual
                float4 rv = *(const float4*)&res[(size_t)row * N + col];
                v0 += rv.x; v1 += rv.y; v2 += rv.z; v3 += rv.w;
            }
            *(float4*)&C[(size_t)row * N + col] = make_float4(v0, v1, v2, v3);
        }
    }
}

// ---------------- Flash attention (fp32, Br=Bc=64, Dh=64, FFMA2) ----------------
// grid: (L/64, B*H), block: 256 (16x16 microtile threads)
#define AP 66    // padded pitch; 66*4B = 264B rows -> 8B-aligned column pairs
__global__ __launch_bounds__(256) void attn_kernel(const float* __restrict__ qkv,
                                                   float* __restrict__ ctx) {
    extern __shared__ float sm[];
    float* Qs = sm;                         // [64][AP]  (d-major: Qs[d][i])
    float* Ks = sm + 64 * AP;               // [64][AP]  (d-major: Ks[d][j])
    float* Vs = sm + 2 * 64 * AP;           // [64][64]  (natural: Vs[k][dd])
    float* Ps = sm + 2 * 64 * AP + 64 * 64; // [64][AP]  (k-major: Ps[k][i])

    int tid  = threadIdx.x;
    int trow = tid >> 4;   // 0..15 -> owns rows trow*4..+3
    int tcol = tid & 15;   // 0..15 -> owns cols tcol*4..+3
    int qb = blockIdx.x;
    int bh = blockIdx.y;
    int bb = bh >> 4;
    int h  = bh & 15;

    // load Q tile (64 x 64), transposed into Qs[d][i]
    const float* qbase = qkv + ((size_t)(bb * LSEQ + qb * 64)) * (3 * D_MODEL) + h * HDIM;
    for (int t = tid; t < 1024; t += 256) {
        int row = t >> 4;
        int c4  = (t & 15) << 2;
        float4 v = *(const float4*)(qbase + (size_t)row * (3 * D_MODEL) + c4);
        Qs[(c4 + 0) * AP + row] = v.x;
        Qs[(c4 + 1) * AP + row] = v.y;
        Qs[(c4 + 2) * AP + row] = v.z;
        Qs[(c4 + 3) * AP + row] = v.w;
    }

    u64 acc2O[4][2] = {};          // 4 rows x 2 col-pairs (packed f32x2)
    float mrow[4], lrow[4];
    #pragma unroll
    for (int r = 0; r < 4; r++) { mrow[r] = -INFINITY; lrow[r] = 0.f; }

    for (int kb = 0; kb < LSEQ / 64; kb++) {
        __syncthreads();   // protect Ks/Vs/Ps from previous iteration's readers
        const float* kbase = qkv + ((size_t)(bb * LSEQ + kb * 64)) * (3 * D_MODEL)
                             + D_MODEL + h * HDIM;
        const float* vbase = kbase + D_MODEL;
        for (int t = tid; t < 1024; t += 256) {
            int row = t >> 4;
            int c4  = (t & 15) << 2;
            float4 kv = *(const float4*)(kbase + (size_t)row * (3 * D_MODEL) + c4);
            Ks[(c4 + 0) * AP + row] = kv.x;
            Ks[(c4 + 1) * AP + row] = kv.y;
            Ks[(c4 + 2) * AP + row] = kv.z;
            Ks[(c4 + 3) * AP + row] = kv.w;
            float4 vv = *(const float4*)(vbase + (size_t)row * (3 * D_MODEL) + c4);
            *(float4*)&Vs[row * 64 + c4] = vv;
        }
        __syncthreads();

        // S = Q @ K^T  (4x4 microtile, rank-1 over d, FFMA2 pairs along c)
        u64 acc2S[4][2] = {};
        #pragma unroll 8
        for (int d = 0; d < 64; d++) {
            float a0 = Qs[d * AP + trow * 4 + 0];
            float a1 = Qs[d * AP + trow * 4 + 1];
            float a2v = Qs[d * AP + trow * 4 + 2];
            float a3 = Qs[d * AP + trow * 4 + 3];
            const u64* kp = (const u64*)&Ks[d * AP + tcol * 4];  // 8B-aligned
            u64 b0 = kp[0], b1 = kp[1];
            u64 d0 = pack2(a0, a0); ffma2(acc2S[0][0], d0, b0); ffma2(acc2S[0][1], d0, b1);
            u64 d1 = pack2(a1, a1); ffma2(acc2S[1][0], d1, b0); ffma2(acc2S[1][1], d1, b1);
            u64 d2 = pack2(a2v, a2v); ffma2(acc2S[2][0], d2, b0); ffma2(acc2S[2][1], d2, b1);
            u64 d3 = pack2(a3, a3); ffma2(acc2S[3][0], d3, b0); ffma2(acc2S[3][1], d3, b1);
        }
        float accS[4][4];
        #pragma unroll
        for (int r = 0; r < 4; r++) {
            float2 p0 = unpack2(acc2S[r][0]);
            float2 p1 = unpack2(acc2S[r][1]);
            accS[r][0] = p0.x; accS[r][1] = p0.y;
            accS[r][2] = p1.x; accS[r][3] = p1.y;
        }

        // online softmax (row groups of 16 tx-threads live in one half-warp)
        float alpha[4];
        #pragma unroll
        for (int r = 0; r < 4; r++) {
            float rmax = -INFINITY;
            #pragma unroll
            for (int c = 0; c < 4; c++) {
                accS[r][c] *= 0.125f;   // 1/sqrt(64)
                rmax = fmaxf(rmax, accS[r][c]);
            }
            #pragma unroll
            for (int o = 8; o > 0; o >>= 1)
                rmax = fmaxf(rmax, __shfl_xor_sync(0xffffffffu, rmax, o, 16));
            float mnew = fmaxf(mrow[r], rmax);
            alpha[r] = __expf(mrow[r] - mnew);
            float rsum = 0.f;
            #pragma unroll
            for (int c = 0; c < 4; c++) {
                float p = __expf(accS[r][c] - mnew);
                accS[r][c] = p;
                rsum += p;
            }
            #pragma unroll
            for (int o = 8; o > 0; o >>= 1)
                rsum += __shfl_xor_sync(0xffffffffu, rsum, o, 16);
            lrow[r] = lrow[r] * alpha[r] + rsum;
            mrow[r] = mnew;
        }

        // store P transposed: Ps[k][i]
        #pragma unroll
        for (int r = 0; r < 4; r++)
            #pragma unroll
            for (int c = 0; c < 4; c++)
                Ps[(tcol * 4 + c) * AP + trow * 4 + r] = accS[r][c];
        __syncthreads();

        // O = O*alpha + P @ V   (FFMA2 pairs along c)
        #pragma unroll
        for (int r = 0; r < 4; r++) {
            u64 al2 = pack2(alpha[r], alpha[r]);
            acc2O[r][0] = mul2(acc2O[r][0], al2);
            acc2O[r][1] = mul2(acc2O[r][1], al2);
        }
        #pragma unroll 8
        for (int k = 0; k < 64; k++) {
            float a0 = Ps[k * AP + trow * 4 + 0];
            float a1 = Ps[k * AP + trow * 4 + 1];
            float a2v = Ps[k * AP + trow * 4 + 2];
            float a3 = Ps[k * AP + trow * 4 + 3];
            const u64* vp = (const u64*)&Vs[k * 64 + tcol * 4];  // 8B-aligned
            u64 b0 = vp[0], b1 = vp[1];
            u64 d0 = pack2(a0, a0); ffma2(acc2O[0][0], d0, b0); ffma2(acc2O[0][1], d0, b1);
            u64 d1 = pack2(a1, a1); ffma2(acc2O[1][0], d1, b0); ffma2(acc2O[1][1], d1, b1);
            u64 d2 = pack2(a2v, a2v); ffma2(acc2O[2][0], d2, b0); ffma2(acc2O[2][1], d2, b1);
            u64 d3 = pack2(a3, a3); ffma2(acc2O[3][0], d3, b0); ffma2(acc2O[3][1], d3, b1);
        }
    }

    // normalize and write ctx[b, q, h*64 + dd]
    #pragma unroll
    for (int r = 0; r < 4; r++) {
        float inv = 1.0f / lrow[r];
        int orow = bb * LSEQ + qb * 64 + trow * 4 + r;
        float2 p0 = unpack2(acc2O[r][0]);
        float2 p1 = unpack2(acc2O[r][1]);
        float4 o = make_float4(p0.x * inv, p0.y * inv, p1.x * inv, p1.y * inv);
        *(float4*)&ctx[(size_t)orow * D_MODEL + h * HDIM + tcol * 4] = o;
    }
}

#define ATTN_SMEM ((2 * 64 * AP + 64 * 64 + 64 * AP) * 4)

// ---------------- launch ----------------
extern "C" void kernel_launch(void* const* d_in, const int* in_sizes, int n_in,
                              void* d_out, int out_size) {
    (void)in_sizes; (void)n_in; (void)out_size;
    const float* x     = (const float*)d_in[0];
    const float* qkv_w = (const float*)d_in[1];
    const float* qkv_b = (const float*)d_in[2];
    const float* out_w = (const float*)d_in[3];
    const float* out_b = (const float*)d_in[4];
    const float* ff1_w = (const float*)d_in[5];
    const float* ff1_b = (const float*)d_in[6];
    const float* ff2_w = (const float*)d_in[7];
    const float* ff2_b = (const float*)d_in[8];
    const float* ln1_g = (const float*)d_in[9];
    const float* ln1_b = (const float*)d_in[10];
    const float* ln2_g = (const float*)d_in[11];
    const float* ln2_b = (const float*)d_in[12];
    float* out = (float*)d_out;

    float *h, *qkvbuf, *ctx, *x1, *ff;
    cudaGetSymbolAddress((void**)&h,      g_h);
    cudaGetSymbolAddress((void**)&qkvbuf, g_qkv);
    cudaGetSymbolAddress((void**)&ctx,    g_ctx);
    cudaGetSymbolAddress((void**)&x1,     g_x1);
    cudaGetSymbolAddress((void**)&ff,     g_ff);

    cudaFuncSetAttribute(attn_kernel,
                         cudaFuncAttributeMaxDynamicSharedMemorySize, ATTN_SMEM);

    // 1) h = LN1(x)
    ln_kernel<<<NTOK, 256>>>(x, ln1_g, ln1_b, h);
    // 2) qkv = h @ qkv_w + qkv_b      [8192, 3072]
    sgemm<0><<<dim3(3 * D_MODEL / 128, NTOK / 128), 256>>>(
        NTOK, 3 * D_MODEL, D_MODEL, h, qkv_w, qkv_b, nullptr, qkvbuf);
    // 3) ctx = attention(qkv)
    attn_kernel<<<dim3(LSEQ / 64, 4 * NHEAD), 256, ATTN_SMEM>>>(qkvbuf, ctx);
    // 4) x1 = x + ctx @ out_w + out_b
    sgemm<2><<<dim3(D_MODEL / 128, NTOK / 128), 256>>>(
        NTOK, D_MODEL, D_MODEL, ctx, out_w, out_b, x, x1);
    // 5) h = LN2(x1)
    ln_kernel<<<NTOK, 256>>>(x1, ln2_g, ln2_b, h);
    // 6) ff = gelu(h @ ff1_w + ff1_b)  [8192, 2048]
    sgemm<1><<<dim3(FFH / 128, NTOK / 128), 256>>>(
        NTOK, FFH, D_MODEL, h, ff1_w, ff1_b, nullptr, ff);
    // 7) out = x1 + ff @ ff2_w + ff2_b
    sgemm<2><<<dim3(D_MODEL / 128, NTOK / 128), 256>>>(
        NTOK, D_MODEL, FFH, ff, ff2_w, ff2_b, x1, out);
}

// round 8
// speedup vs baseline: 2.0572x; 2.0572x over previous
#include <cuda_runtime.h>
#include <cuda_bf16.h>
#include <math.h>
#include <stdint.h>

#define D_MODEL 1024
#define LSEQ    2048
#define NTOK    8192          // B * L
#define NHEAD   16
#define HDIM    64
#define FFH     2048

typedef __nv_bfloat16 bf16;

// ==================== PTX helpers (all plain-sm_103-safe: sm_80-era) ====================
__device__ __forceinline__ uint32_t smem_u32(const void* p) {
    uint32_t a;
    asm("{ .reg .u64 t; cvta.to.shared.u64 t, %1; cvt.u32.u64 %0, t; }" : "=r"(a) : "l"(p));
    return a;
}
__device__ __forceinline__ void cp16(uint32_t dst, const void* src) {
    asm volatile("cp.async.ca.shared.global [%0], [%1], 16;" :: "r"(dst), "l"(src) : "memory");
}
__device__ __forceinline__ void cp_commit() {
    asm volatile("cp.async.commit_group;" ::: "memory");
}
template<int N> __device__ __forceinline__ void cp_wait() {
    asm volatile("cp.async.wait_group %0;" :: "n"(N) : "memory");
}
__device__ __forceinline__ void ldm4(uint32_t* r, uint32_t a) {
    asm volatile("ldmatrix.sync.aligned.m8n8.x4.shared.b16 {%0,%1,%2,%3}, [%4];"
                 : "=r"(r[0]), "=r"(r[1]), "=r"(r[2]), "=r"(r[3]) : "r"(a));
}
__device__ __forceinline__ void ldm2(uint32_t* r, uint32_t a) {
    asm volatile("ldmatrix.sync.aligned.m8n8.x2.shared.b16 {%0,%1}, [%2];"
                 : "=r"(r[0]), "=r"(r[1]) : "r"(a));
}
__device__ __forceinline__ void mma16816(float* c, const uint32_t* a, const uint32_t* b) {
    asm volatile("mma.sync.aligned.m16n8k16.row.col.f32.bf16.bf16.f32 "
                 "{%0,%1,%2,%3}, {%4,%5,%6,%7}, {%8,%9}, {%0,%1,%2,%3};"
                 : "+f"(c[0]), "+f"(c[1]), "+f"(c[2]), "+f"(c[3])
                 : "r"(a[0]), "r"(a[1]), "r"(a[2]), "r"(a[3]), "r"(b[0]), "r"(b[1]));
}
__device__ __forceinline__ void bsplit(float v, unsigned short& h, unsigned short& l) {
    bf16 hb = __float2bfloat16(v);
    bf16 lb = __float2bfloat16(v - __bfloat162float(hb));
    h = __bfloat16_as_ushort(hb);
    l = __bfloat16_as_ushort(lb);
}

// ==================== scratch ====================
__device__ float g_qkv[NTOK * 3 * D_MODEL];     // f32 QKV (attention input)
__device__ float g_x1 [NTOK * D_MODEL];         // post-attention residual (f32)
__device__ bf16  g_h_hi [NTOK * D_MODEL],  g_h_lo [NTOK * D_MODEL];    // LN outs
__device__ bf16  g_ctx_hi[NTOK * D_MODEL], g_ctx_lo[NTOK * D_MODEL];   // attn ctx
__device__ bf16  g_ff_hi[NTOK * FFH],      g_ff_lo[NTOK * FFH];        // FF1 out
// transposed + split weights: [N][K] K-major
__device__ bf16  g_wqkvT_hi[3 * D_MODEL * D_MODEL], g_wqkvT_lo[3 * D_MODEL * D_MODEL];
__device__ bf16  g_woutT_hi[D_MODEL * D_MODEL],     g_woutT_lo[D_MODEL * D_MODEL];
__device__ bf16  g_wff1T_hi[FFH * D_MODEL],         g_wff1T_lo[FFH * D_MODEL];
__device__ bf16  g_wff2T_hi[D_MODEL * FFH],         g_wff2T_lo[D_MODEL * FFH];

// ==================== weight transpose+split:  T[n][k] = W[k][n] ====================
__global__ __launch_bounds__(256) void wconv(const float* __restrict__ W, int K, int N,
                                             bf16* __restrict__ Thi, bf16* __restrict__ Tlo) {
    __shared__ float t[32][33];
    int tx = threadIdx.x, ty = threadIdx.y;           // 32 x 8
    int n0 = blockIdx.x * 32, k0 = blockIdx.y * 32;
    #pragma unroll
    for (int i = 0; i < 4; i++) {
        int k = k0 + ty + i * 8;
        t[ty + i * 8][tx] = W[(size_t)k * N + n0 + tx];
    }
    __syncthreads();
    #pragma unroll
    for (int i = 0; i < 4; i++) {
        int n = n0 + ty + i * 8;
        float v = t[tx][ty + i * 8];
        unsigned short h, l;
        bsplit(v, h, l);
        Thi[(size_t)n * K + k0 + tx] = __ushort_as_bfloat16(h);
        Tlo[(size_t)n * K + k0 + tx] = __ushort_as_bfloat16(l);
    }
}

// ==================== LayerNorm -> bf16 hi/lo ====================
__global__ __launch_bounds__(256) void ln_kernel(const float* __restrict__ x,
                                                 const float* __restrict__ g,
                                                 const float* __restrict__ b,
                                                 bf16* __restrict__ ohi,
                                                 bf16* __restrict__ olo) {
    int row = blockIdx.x;
    int t = threadIdx.x;
    const float4* xr = (const float4*)(x + (size_t)row * D_MODEL);
    float4 v = xr[t];
    float s  = v.x + v.y + v.z + v.w;
    float ss = v.x*v.x + v.y*v.y + v.z*v.z + v.w*v.w;
    #pragma unroll
    for (int o = 16; o > 0; o >>= 1) {
        s  += __shfl_xor_sync(0xffffffffu, s,  o);
        ss += __shfl_xor_sync(0xffffffffu, ss, o);
    }
    __shared__ float ssum[8], ssq[8];
    __shared__ float stats[2];
    int warp = t >> 5, lane = t & 31;
    if (lane == 0) { ssum[warp] = s; ssq[warp] = ss; }
    __syncthreads();
    if (t == 0) {
        float S = 0.f, SS = 0.f;
        #pragma unroll
        for (int i = 0; i < 8; i++) { S += ssum[i]; SS += ssq[i]; }
        float mu  = S * (1.0f / D_MODEL);
        float var = SS * (1.0f / D_MODEL) - mu * mu;
        stats[0] = mu;
        stats[1] = rsqrtf(var + 1e-5f);
    }
    __syncthreads();
    float mu = stats[0], rstd = stats[1];
    float4 gg = ((const float4*)g)[t];
    float4 bb = ((const float4*)b)[t];
    float o0 = (v.x - mu) * rstd * gg.x + bb.x;
    float o1 = (v.y - mu) * rstd * gg.y + bb.y;
    float o2 = (v.z - mu) * rstd * gg.z + bb.z;
    float o3 = (v.w - mu) * rstd * gg.w + bb.w;
    unsigned short h0,h1,h2,h3,l0,l1,l2,l3;
    bsplit(o0,h0,l0); bsplit(o1,h1,l1); bsplit(o2,h2,l2); bsplit(o3,h3,l3);
    uint2 hv = make_uint2((uint32_t)h0 | ((uint32_t)h1 << 16), (uint32_t)h2 | ((uint32_t)h3 << 16));
    uint2 lv = make_uint2((uint32_t)l0 | ((uint32_t)l1 << 16), (uint32_t)l2 | ((uint32_t)l3 << 16));
    ((uint2*)(ohi + (size_t)row * D_MODEL))[t] = hv;
    ((uint2*)(olo + (size_t)row * D_MODEL))[t] = lv;
}

// ==================== mma.sync GEMM: C[M,N] = A @ B^T  (3xBF16 split) ====================
// A: [M,K] bf16 hi/lo (K contig). B: [N,K] bf16 hi/lo (K contig, i.e. B^T K-major).
// Block tile 128x128, BK=32, 8 warps (2m x 4n), warp tile 64x32 (4 m16 x 4 n8 frags).
// cp.async double buffer; smem rows padded to 80B (conflict-free ldmatrix).
// EPI: 0 = bias -> f32 C ; 1 = bias+GELU -> bf16 hi/lo ; 2 = bias+residual -> f32 C
#define STAGE_B   40960                // 4 matrices * 128 rows * 80 B
#define MTX_B     10240
#define GEMM_SMEM (2 * STAGE_B)

template<int EPI>
__global__ __launch_bounds__(256, 1) void gemm_mma(
    int K, int N,
    const bf16* __restrict__ Ahi, const bf16* __restrict__ Alo,
    const bf16* __restrict__ Bhi, const bf16* __restrict__ Blo,
    const float* __restrict__ bias, const float* __restrict__ res,
    float* __restrict__ C, bf16* __restrict__ Chi, bf16* __restrict__ Clo) {
    extern __shared__ __align__(128) char smem[];
    uint32_t sb = smem_u32(smem);
    const int tid  = threadIdx.x;
    const int lane = tid & 31;
    const int wid  = tid >> 5;
    const int warp_m = wid >> 2;      // 0..1
    const int warp_n = wid & 3;       // 0..3
    const int bm = blockIdx.y * 128;
    const int bn = blockIdx.x * 128;

    const bf16* srcs[4] = { Ahi + (size_t)bm * K, Alo + (size_t)bm * K,
                            Bhi + (size_t)bn * K, Blo + (size_t)bn * K };

    const int nchunk = K >> 5;
    float acc[4][4][4] = {};

    // per-thread load coords: 512 16B-chunks per matrix, 2 per thread
    const int c0row = tid >> 2, c0q = tid & 3;            // chunk tid
    const int c1row = (tid + 256) >> 2, c1q = tid & 3;    // chunk tid+256

    auto load_stage = [&](int ch) {
        uint32_t stg = sb + (uint32_t)(ch & 1) * STAGE_B;
        int k0 = ch << 5;
        #pragma unroll
        for (int mtx = 0; mtx < 4; mtx++) {
            const bf16* s = srcs[mtx];
            cp16(stg + mtx * MTX_B + c0row * 80 + c0q * 16,
                 s + (size_t)c0row * K + k0 + c0q * 8);
            cp16(stg + mtx * MTX_B + c1row * 80 + c1q * 16,
                 s + (size_t)c1row * K + k0 + c1q * 8);
        }
        cp_commit();
    };

    load_stage(0);
    for (int ch = 0; ch < nchunk; ch++) {
        if (ch + 1 < nchunk) { load_stage(ch + 1); cp_wait<1>(); }
        else                 { cp_wait<0>(); }
        __syncthreads();

        uint32_t stg = sb + (uint32_t)(ch & 1) * STAGE_B;
        const int arow = lane & 15, ahalf = lane >> 4;
        const int bid = lane & 15, bnrow = bid & 7, bkh = bid >> 3;
        #pragma unroll
        for (int ks = 0; ks < 32; ks += 16) {
            uint32_t ah[4][4], al[4][4];
            #pragma unroll
            for (int mt = 0; mt < 4; mt++) {
                uint32_t off = (uint32_t)(warp_m * 64 + mt * 16 + arow) * 80
                             + (uint32_t)(ks + ahalf * 8) * 2;
                ldm4(ah[mt], stg + off);
                ldm4(al[mt], stg + MTX_B + off);
            }
            uint32_t bh[4][2], bl[4][2];
            #pragma unroll
            for (int nt = 0; nt < 4; nt++) {
                uint32_t off = (uint32_t)(warp_n * 32 + nt * 8 + bnrow) * 80
                             + (uint32_t)(ks + bkh * 8) * 2;
                ldm2(bh[nt], stg + 2 * MTX_B + off);
                ldm2(bl[nt], stg + 3 * MTX_B + off);
            }
            #pragma unroll
            for (int mt = 0; mt < 4; mt++)
                #pragma unroll
                for (int nt = 0; nt < 4; nt++) {
                    mma16816(acc[mt][nt], ah[mt], bh[nt]);
                    mma16816(acc[mt][nt], ah[mt], bl[nt]);
                    mma16816(acc[mt][nt], al[mt], bh[nt]);
                }
        }
        __syncthreads();
    }

    // epilogue — fragment c: d0,d1 at (row=lane/4, col=2*(lane%4)+{0,1}); d2,d3 at row+8
    #pragma unroll
    for (int mt = 0; mt < 4; mt++) {
        int r0 = bm + warp_m * 64 + mt * 16 + (lane >> 2);
        int r1 = r0 + 8;
        #pragma unroll
        for (int nt = 0; nt < 4; nt++) {
            int cb = bn + warp_n * 32 + nt * 8 + (lane & 3) * 2;
            float2 bs = *(const float2*)&bias[cb];
            float v0 = acc[mt][nt][0] + bs.x;
            float v1 = acc[mt][nt][1] + bs.y;
            float v2 = acc[mt][nt][2] + bs.x;
            float v3 = acc[mt][nt][3] + bs.y;
            if (EPI == 1) {
                v0 = 0.5f * v0 * (1.0f + erff(v0 * 0.70710678118654752f));
                v1 = 0.5f * v1 * (1.0f + erff(v1 * 0.70710678118654752f));
                v2 = 0.5f * v2 * (1.0f + erff(v2 * 0.70710678118654752f));
                v3 = 0.5f * v3 * (1.0f + erff(v3 * 0.70710678118654752f));
                unsigned short h0,h1,h2,h3,l0,l1,l2,l3;
                bsplit(v0,h0,l0); bsplit(v1,h1,l1); bsplit(v2,h2,l2); bsplit(v3,h3,l3);
                *(uint32_t*)(Chi + (size_t)r0 * N + cb) = (uint32_t)h0 | ((uint32_t)h1 << 16);
                *(uint32_t*)(Clo + (size_t)r0 * N + cb) = (uint32_t)l0 | ((uint32_t)l1 << 16);
                *(uint32_t*)(Chi + (size_t)r1 * N + cb) = (uint32_t)h2 | ((uint32_t)h3 << 16);
                *(uint32_t*)(Clo + (size_t)r1 * N + cb) = (uint32_t)l2 | ((uint32_t)l3 << 16);
            } else {
                if (EPI == 2) {
                    float2 q0 = *(const float2*)&res[(size_t)r0 * N + cb];
                    float2 q1 = *(const float2*)&res[(size_t)r1 * N + cb];
                    v0 += q0.x; v1 += q0.y; v2 += q1.x; v3 += q1.y;
                }
                *(float2*)&C[(size_t)r0 * N + cb] = make_float2(v0, v1);
                *(float2*)&C[(size_t)r1 * N + cb] = make_float2(v2, v3);
            }
        }
    }
}

// ==================== Flash attention (fp32, Br=128, Bc=64, 8x4 microtile) ====================
#define QP 129
#define KP 65
#define PP 129
#define ATTN_SMEM ((64 * QP + 64 * KP + 64 * 64 + 64 * PP) * 4)
__global__ __launch_bounds__(256) void attn_kernel(const float* __restrict__ qkv,
                                                   bf16* __restrict__ chi,
                                                   bf16* __restrict__ clo) {
    extern __shared__ float sm[];
    float* Qs = sm;                              // [64 d][QP]  Qs[d][i], i=0..127
    float* Ks = sm + 64 * QP;                    // [64 d][KP]  Ks[d][j], j=0..63
    float* Vs = sm + 64 * QP + 64 * KP;          // [64 k][64]
    float* Ps = sm + 64 * QP + 64 * KP + 64*64;  // [64 k][PP]  Ps[k][i]

    int tid  = threadIdx.x;
    int trow = tid >> 4;   // 0..15 -> rows trow*8..+7
    int tcol = tid & 15;   // 0..15 -> cols tcol*4..+3
    int qb = blockIdx.x;
    int bh = blockIdx.y;
    int bb = bh >> 4;
    int h  = bh & 15;

    const float* qbase = qkv + ((size_t)(bb * LSEQ + qb * 128)) * (3 * D_MODEL) + h * HDIM;
    for (int t = tid; t < 2048; t += 256) {
        int row = t >> 4;
        int c4  = (t & 15) << 2;
        float4 v = *(const float4*)(qbase + (size_t)row * (3 * D_MODEL) + c4);
        Qs[(c4 + 0) * QP + row] = v.x;
        Qs[(c4 + 1) * QP + row] = v.y;
        Qs[(c4 + 2) * QP + row] = v.z;
        Qs[(c4 + 3) * QP + row] = v.w;
    }

    float accO[8][4] = {};
    float mrow[8], lrow[8];
    #pragma unroll
    for (int r = 0; r < 8; r++) { mrow[r] = -INFINITY; lrow[r] = 0.f; }

    for (int kb = 0; kb < LSEQ / 64; kb++) {
        __syncthreads();
        const float* kbase = qkv + ((size_t)(bb * LSEQ + kb * 64)) * (3 * D_MODEL)
                             + D_MODEL + h * HDIM;
        const float* vbase = kbase + D_MODEL;
        for (int t = tid; t < 1024; t += 256) {
            int row = t >> 4;
            int c4  = (t & 15) << 2;
            float4 kv = *(const float4*)(kbase + (size_t)row * (3 * D_MODEL) + c4);
            Ks[(c4 + 0) * KP + row] = kv.x;
            Ks[(c4 + 1) * KP + row] = kv.y;
            Ks[(c4 + 2) * KP + row] = kv.z;
            Ks[(c4 + 3) * KP + row] = kv.w;
            float4 vv = *(const float4*)(vbase + (size_t)row * (3 * D_MODEL) + c4);
            *(float4*)&Vs[row * 64 + c4] = vv;
        }
        __syncthreads();

        float accS[8][4] = {};
        #pragma unroll 4
        for (int d = 0; d < 64; d++) {
            float a[8], b[4];
            #pragma unroll
            for (int r = 0; r < 8; r++) a[r] = Qs[d * QP + trow * 8 + r];
            #pragma unroll
            for (int c = 0; c < 4; c++) b[c] = Ks[d * KP + tcol * 4 + c];
            #pragma unroll
            for (int r = 0; r < 8; r++)
                #pragma unroll
                for (int c = 0; c < 4; c++)
                    accS[r][c] += a[r] * b[c];
        }

        float alpha[8];
        #pragma unroll
        for (int r = 0; r < 8; r++) {
            float rmax = -INFINITY;
            #pragma unroll
            for (int c = 0; c < 4; c++) {
                accS[r][c] *= 0.125f;
                rmax = fmaxf(rmax, accS[r][c]);
            }
            #pragma unroll
            for (int o = 8; o > 0; o >>= 1)
                rmax = fmaxf(rmax, __shfl_xor_sync(0xffffffffu, rmax, o, 16));
            float mnew = fmaxf(mrow[r], rmax);
            alpha[r] = __expf(mrow[r] - mnew);
            float rsum = 0.f;
            #pragma unroll
            for (int c = 0; c < 4; c++) {
                float p = __expf(accS[r][c] - mnew);
                accS[r][c] = p;
                rsum += p;
            }
            #pragma unroll
            for (int o = 8; o > 0; o >>= 1)
                rsum += __shfl_xor_sync(0xffffffffu, rsum, o, 16);
            lrow[r] = lrow[r] * alpha[r] + rsum;
            mrow[r] = mnew;
        }

        #pragma unroll
        for (int r = 0; r < 8; r++)
            #pragma unroll
            for (int c = 0; c < 4; c++)
                Ps[(tcol * 4 + c) * PP + trow * 8 + r] = accS[r][c];
        __syncthreads();

        #pragma unroll
        for (int r = 0; r < 8; r++)
            #pragma unroll
            for (int c = 0; c < 4; c++)
                accO[r][c] *= alpha[r];
        #pragma unroll 4
        for (int k = 0; k < 64; k++) {
            float a[8];
            #pragma unroll
            for (int r = 0; r < 8; r++) a[r] = Ps[k * PP + trow * 8 + r];
            float4 bv = *(const float4*)&Vs[k * 64 + tcol * 4];
            float b[4] = {bv.x, bv.y, bv.z, bv.w};
            #pragma unroll
            for (int r = 0; r < 8; r++)
                #pragma unroll
                for (int c = 0; c < 4; c++)
                    accO[r][c] += a[r] * b[c];
        }
    }

    #pragma unroll
    for (int r = 0; r < 8; r++) {
        float inv = 1.0f / lrow[r];
        int orow = bb * LSEQ + qb * 128 + trow * 8 + r;
        float v0 = accO[r][0] * inv, v1 = accO[r][1] * inv;
        float v2 = accO[r][2] * inv, v3 = accO[r][3] * inv;
        unsigned short h0,h1,h2,h3,l0,l1,l2,l3;
        bsplit(v0,h0,l0); bsplit(v1,h1,l1); bsplit(v2,h2,l2); bsplit(v3,h3,l3);
        uint2 hv = make_uint2((uint32_t)h0 | ((uint32_t)h1 << 16),
                              (uint32_t)h2 | ((uint32_t)h3 << 16));
        uint2 lv = make_uint2((uint32_t)l0 | ((uint32_t)l1 << 16),
                              (uint32_t)l2 | ((uint32_t)l3 << 16));
        size_t off = (size_t)orow * D_MODEL + h * HDIM + tcol * 4;
        *(uint2*)(chi + off) = hv;
        *(uint2*)(clo + off) = lv;
    }
}

// ==================== launch ====================
extern "C" void kernel_launch(void* const* d_in, const int* in_sizes, int n_in,
                              void* d_out, int out_size) {
    (void)in_sizes; (void)n_in; (void)out_size;
    const float* x     = (const float*)d_in[0];
    const float* qkv_w = (const float*)d_in[1];
    const float* qkv_b = (const float*)d_in[2];
    const float* out_w = (const float*)d_in[3];
    const float* out_b = (const float*)d_in[4];
    const float* ff1_w = (const float*)d_in[5];
    const float* ff1_b = (const float*)d_in[6];
    const float* ff2_w = (const float*)d_in[7];
    const float* ff2_b = (const float*)d_in[8];
    const float* ln1_g = (const float*)d_in[9];
    const float* ln1_b = (const float*)d_in[10];
    const float* ln2_g = (const float*)d_in[11];
    const float* ln2_b = (const float*)d_in[12];
    float* out = (float*)d_out;

    float *qkvbuf, *x1;
    bf16 *hhi, *hlo, *chi, *clo, *fhi, *flo;
    bf16 *wqh, *wql, *woh, *wol, *w1h, *w1l, *w2h, *w2l;
    cudaGetSymbolAddress((void**)&qkvbuf, g_qkv);
    cudaGetSymbolAddress((void**)&x1,     g_x1);
    cudaGetSymbolAddress((void**)&hhi, g_h_hi);   cudaGetSymbolAddress((void**)&hlo, g_h_lo);
    cudaGetSymbolAddress((void**)&chi, g_ctx_hi); cudaGetSymbolAddress((void**)&clo, g_ctx_lo);
    cudaGetSymbolAddress((void**)&fhi, g_ff_hi);  cudaGetSymbolAddress((void**)&flo, g_ff_lo);
    cudaGetSymbolAddress((void**)&wqh, g_wqkvT_hi); cudaGetSymbolAddress((void**)&wql, g_wqkvT_lo);
    cudaGetSymbolAddress((void**)&woh, g_woutT_hi); cudaGetSymbolAddress((void**)&wol, g_woutT_lo);
    cudaGetSymbolAddress((void**)&w1h, g_wff1T_hi); cudaGetSymbolAddress((void**)&w1l, g_wff1T_lo);
    cudaGetSymbolAddress((void**)&w2h, g_wff2T_hi); cudaGetSymbolAddress((void**)&w2l, g_wff2T_lo);

    cudaFuncSetAttribute(gemm_mma<0>, cudaFuncAttributeMaxDynamicSharedMemorySize, GEMM_SMEM);
    cudaFuncSetAttribute(gemm_mma<1>, cudaFuncAttributeMaxDynamicSharedMemorySize, GEMM_SMEM);
    cudaFuncSetAttribute(gemm_mma<2>, cudaFuncAttributeMaxDynamicSharedMemorySize, GEMM_SMEM);
    cudaFuncSetAttribute(attn_kernel, cudaFuncAttributeMaxDynamicSharedMemorySize, ATTN_SMEM);

    dim3 tb(32, 8);
    // weight transpose + hi/lo split
    wconv<<<dim3(3 * D_MODEL / 32, D_MODEL / 32), tb>>>(qkv_w, D_MODEL, 3 * D_MODEL, wqh, wql);
    wconv<<<dim3(D_MODEL / 32, D_MODEL / 32), tb>>>(out_w, D_MODEL, D_MODEL, woh, wol);
    wconv<<<dim3(FFH / 32, D_MODEL / 32), tb>>>(ff1_w, D_MODEL, FFH, w1h, w1l);
    wconv<<<dim3(D_MODEL / 32, FFH / 32), tb>>>(ff2_w, FFH, D_MODEL, w2h, w2l);

    // 1) h = LN1(x)
    ln_kernel<<<NTOK, 256>>>(x, ln1_g, ln1_b, hhi, hlo);
    // 2) qkv = h @ qkv_w + b   -> f32
    gemm_mma<0><<<dim3(3 * D_MODEL / 128, NTOK / 128), 256, GEMM_SMEM>>>(
        D_MODEL, 3 * D_MODEL, hhi, hlo, wqh, wql, qkv_b, nullptr, qkvbuf, nullptr, nullptr);
    // 3) ctx = attention(qkv) -> bf16 hi/lo
    attn_kernel<<<dim3(LSEQ / 128, 4 * NHEAD), 256, ATTN_SMEM>>>(qkvbuf, chi, clo);
    // 4) x1 = x + ctx @ out_w + b
    gemm_mma<2><<<dim3(D_MODEL / 128, NTOK / 128), 256, GEMM_SMEM>>>(
        D_MODEL, D_MODEL, chi, clo, woh, wol, out_b, x, x1, nullptr, nullptr);
    // 5) h = LN2(x1)
    ln_kernel<<<NTOK, 256>>>(x1, ln2_g, ln2_b, hhi, hlo);
    // 6) ff = gelu(h @ ff1_w + b) -> bf16 hi/lo
    gemm_mma<1><<<dim3(FFH / 128, NTOK / 128), 256, GEMM_SMEM>>>(
        D_MODEL, FFH, hhi, hlo, w1h, w1l, ff1_b, nullptr, nullptr, fhi, flo);
    // 7) out = x1 + ff @ ff2_w + b
    gemm_mma<2><<<dim3(D_MODEL / 128, NTOK / 128), 256, GEMM_SMEM>>>(
        FFH, D_MODEL, fhi, flo, w2h, w2l, ff2_b, x1, out, nullptr, nullptr);
}

// round 9
// speedup vs baseline: 3.1554x; 1.5338x over previous
#include <cuda_runtime.h>
#include <cuda_bf16.h>
#include <math.h>
#include <stdint.h>

#define D_MODEL 1024
#define LSEQ    2048
#define NTOK    8192          // B * L
#define NHEAD   16
#define HDIM    64
#define FFH     2048

typedef __nv_bfloat16 bf16;

// ==================== PTX helpers (plain-sm_103-safe: sm_80-era only) ====================
__device__ __forceinline__ uint32_t smem_u32(const void* p) {
    uint32_t a;
    asm("{ .reg .u64 t; cvta.to.shared.u64 t, %1; cvt.u32.u64 %0, t; }" : "=r"(a) : "l"(p));
    return a;
}
__device__ __forceinline__ void cp16(uint32_t dst, const void* src) {
    asm volatile("cp.async.ca.shared.global [%0], [%1], 16;" :: "r"(dst), "l"(src) : "memory");
}
__device__ __forceinline__ void cp_commit() {
    asm volatile("cp.async.commit_group;" ::: "memory");
}
template<int N> __device__ __forceinline__ void cp_wait() {
    asm volatile("cp.async.wait_group %0;" :: "n"(N) : "memory");
}
__device__ __forceinline__ void ldm4(uint32_t* r, uint32_t a) {
    asm volatile("ldmatrix.sync.aligned.m8n8.x4.shared.b16 {%0,%1,%2,%3}, [%4];"
                 : "=r"(r[0]), "=r"(r[1]), "=r"(r[2]), "=r"(r[3]) : "r"(a));
}
__device__ __forceinline__ void ldm4t(uint32_t* r, uint32_t a) {
    asm volatile("ldmatrix.sync.aligned.m8n8.x4.trans.shared.b16 {%0,%1,%2,%3}, [%4];"
                 : "=r"(r[0]), "=r"(r[1]), "=r"(r[2]), "=r"(r[3]) : "r"(a));
}
__device__ __forceinline__ void ldm2(uint32_t* r, uint32_t a) {
    asm volatile("ldmatrix.sync.aligned.m8n8.x2.shared.b16 {%0,%1}, [%2];"
                 : "=r"(r[0]), "=r"(r[1]) : "r"(a));
}
__device__ __forceinline__ void mma16816(float* c, const uint32_t* a, const uint32_t* b) {
    asm volatile("mma.sync.aligned.m16n8k16.row.col.f32.bf16.bf16.f32 "
                 "{%0,%1,%2,%3}, {%4,%5,%6,%7}, {%8,%9}, {%0,%1,%2,%3};"
                 : "+f"(c[0]), "+f"(c[1]), "+f"(c[2]), "+f"(c[3])
                 : "r"(a[0]), "r"(a[1]), "r"(a[2]), "r"(a[3]), "r"(b[0]), "r"(b[1]));
}
__device__ __forceinline__ void bsplit(float v, unsigned short& h, unsigned short& l) {
    bf16 hb = __float2bfloat16(v);
    bf16 lb = __float2bfloat16(v - __bfloat162float(hb));
    h = __bfloat16_as_ushort(hb);
    l = __bfloat16_as_ushort(lb);
}
__device__ __forceinline__ void packsplit2(float a, float b, uint32_t& ph, uint32_t& pl) {
    unsigned short ha, la, hb, lb;
    bsplit(a, ha, la); bsplit(b, hb, lb);
    ph = (uint32_t)ha | ((uint32_t)hb << 16);
    pl = (uint32_t)la | ((uint32_t)lb << 16);
}

// ==================== scratch ====================
__device__ float g_x1 [NTOK * D_MODEL];         // post-attention residual (f32)
__device__ bf16  g_h_hi [NTOK * D_MODEL],  g_h_lo [NTOK * D_MODEL];    // LN outs
__device__ bf16  g_qkv_hi[NTOK * 3 * D_MODEL], g_qkv_lo[NTOK * 3 * D_MODEL];
__device__ bf16  g_ctx_hi[NTOK * D_MODEL], g_ctx_lo[NTOK * D_MODEL];   // attn ctx
__device__ bf16  g_ff_hi[NTOK * FFH],      g_ff_lo[NTOK * FFH];        // FF1 out
// transposed + split weights: [N][K] K-major
__device__ bf16  g_wqkvT_hi[3 * D_MODEL * D_MODEL], g_wqkvT_lo[3 * D_MODEL * D_MODEL];
__device__ bf16  g_woutT_hi[D_MODEL * D_MODEL],     g_woutT_lo[D_MODEL * D_MODEL];
__device__ bf16  g_wff1T_hi[FFH * D_MODEL],         g_wff1T_lo[FFH * D_MODEL];
__device__ bf16  g_wff2T_hi[D_MODEL * FFH],         g_wff2T_lo[D_MODEL * FFH];

// ==================== weight transpose+split:  T[n][k] = W[k][n] ====================
__global__ __launch_bounds__(256) void wconv(const float* __restrict__ W, int K, int N,
                                             bf16* __restrict__ Thi, bf16* __restrict__ Tlo) {
    __shared__ float t[32][33];
    int tx = threadIdx.x, ty = threadIdx.y;           // 32 x 8
    int n0 = blockIdx.x * 32, k0 = blockIdx.y * 32;
    #pragma unroll
    for (int i = 0; i < 4; i++) {
        int k = k0 + ty + i * 8;
        t[ty + i * 8][tx] = W[(size_t)k * N + n0 + tx];
    }
    __syncthreads();
    #pragma unroll
    for (int i = 0; i < 4; i++) {
        int n = n0 + ty + i * 8;
        float v = t[tx][ty + i * 8];
        unsigned short h, l;
        bsplit(v, h, l);
        Thi[(size_t)n * K + k0 + tx] = __ushort_as_bfloat16(h);
        Tlo[(size_t)n * K + k0 + tx] = __ushort_as_bfloat16(l);
    }
}

// ==================== LayerNorm -> bf16 hi/lo ====================
__global__ __launch_bounds__(256) void ln_kernel(const float* __restrict__ x,
                                                 const float* __restrict__ g,
                                                 const float* __restrict__ b,
                                                 bf16* __restrict__ ohi,
                                                 bf16* __restrict__ olo) {
    int row = blockIdx.x;
    int t = threadIdx.x;
    const float4* xr = (const float4*)(x + (size_t)row * D_MODEL);
    float4 v = xr[t];
    float s  = v.x + v.y + v.z + v.w;
    float ss = v.x*v.x + v.y*v.y + v.z*v.z + v.w*v.w;
    #pragma unroll
    for (int o = 16; o > 0; o >>= 1) {
        s  += __shfl_xor_sync(0xffffffffu, s,  o);
        ss += __shfl_xor_sync(0xffffffffu, ss, o);
    }
    __shared__ float ssum[8], ssq[8];
    __shared__ float stats[2];
    int warp = t >> 5, lane = t & 31;
    if (lane == 0) { ssum[warp] = s; ssq[warp] = ss; }
    __syncthreads();
    if (t == 0) {
        float S = 0.f, SS = 0.f;
        #pragma unroll
        for (int i = 0; i < 8; i++) { S += ssum[i]; SS += ssq[i]; }
        float mu  = S * (1.0f / D_MODEL);
        float var = SS * (1.0f / D_MODEL) - mu * mu;
        stats[0] = mu;
        stats[1] = rsqrtf(var + 1e-5f);
    }
    __syncthreads();
    float mu = stats[0], rstd = stats[1];
    float4 gg = ((const float4*)g)[t];
    float4 bb = ((const float4*)b)[t];
    float o0 = (v.x - mu) * rstd * gg.x + bb.x;
    float o1 = (v.y - mu) * rstd * gg.y + bb.y;
    float o2 = (v.z - mu) * rstd * gg.z + bb.z;
    float o3 = (v.w - mu) * rstd * gg.w + bb.w;
    unsigned short h0,h1,h2,h3,l0,l1,l2,l3;
    bsplit(o0,h0,l0); bsplit(o1,h1,l1); bsplit(o2,h2,l2); bsplit(o3,h3,l3);
    uint2 hv = make_uint2((uint32_t)h0 | ((uint32_t)h1 << 16), (uint32_t)h2 | ((uint32_t)h3 << 16));
    uint2 lv = make_uint2((uint32_t)l0 | ((uint32_t)l1 << 16), (uint32_t)l2 | ((uint32_t)l3 << 16));
    ((uint2*)(ohi + (size_t)row * D_MODEL))[t] = hv;
    ((uint2*)(olo + (size_t)row * D_MODEL))[t] = lv;
}

// ==================== mma.sync GEMM: C[M,N] = A @ B^T  (3xBF16 split) ====================
// EPI: 1 = bias+GELU -> bf16 hi/lo ; 2 = bias+residual -> f32 C ; 3 = bias -> bf16 hi/lo
#define STAGE_B   40960                // 4 matrices * 128 rows * 80 B
#define MTX_B     10240
#define GEMM_SMEM (2 * STAGE_B)

template<int EPI>
__global__ __launch_bounds__(256, 1) void gemm_mma(
    int K, int N,
    const bf16* __restrict__ Ahi, const bf16* __restrict__ Alo,
    const bf16* __restrict__ Bhi, const bf16* __restrict__ Blo,
    const float* __restrict__ bias, const float* __restrict__ res,
    float* __restrict__ C, bf16* __restrict__ Chi, bf16* __restrict__ Clo) {
    extern __shared__ __align__(128) char smem[];
    uint32_t sb = smem_u32(smem);
    const int tid  = threadIdx.x;
    const int lane = tid & 31;
    const int wid  = tid >> 5;
    const int warp_m = wid >> 2;      // 0..1
    const int warp_n = wid & 3;       // 0..3
    const int bm = blockIdx.y * 128;
    const int bn = blockIdx.x * 128;

    const bf16* srcs[4] = { Ahi + (size_t)bm * K, Alo + (size_t)bm * K,
                            Bhi + (size_t)bn * K, Blo + (size_t)bn * K };

    const int nchunk = K >> 5;
    float acc[4][4][4] = {};

    const int c0row = tid >> 2, c0q = tid & 3;
    const int c1row = (tid + 256) >> 2, c1q = tid & 3;

    auto load_stage = [&](int ch) {
        uint32_t stg = sb + (uint32_t)(ch & 1) * STAGE_B;
        int k0 = ch << 5;
        #pragma unroll
        for (int mtx = 0; mtx < 4; mtx++) {
            const bf16* s = srcs[mtx];
            cp16(stg + mtx * MTX_B + c0row * 80 + c0q * 16,
                 s + (size_t)c0row * K + k0 + c0q * 8);
            cp16(stg + mtx * MTX_B + c1row * 80 + c1q * 16,
                 s + (size_t)c1row * K + k0 + c1q * 8);
        }
        cp_commit();
    };

    load_stage(0);
    for (int ch = 0; ch < nchunk; ch++) {
        if (ch + 1 < nchunk) { load_stage(ch + 1); cp_wait<1>(); }
        else                 { cp_wait<0>(); }
        __syncthreads();

        uint32_t stg = sb + (uint32_t)(ch & 1) * STAGE_B;
        const int arow = lane & 15, ahalf = lane >> 4;
        const int bid = lane & 15, bnrow = bid & 7, bkh = bid >> 3;
        #pragma unroll
        for (int ks = 0; ks < 32; ks += 16) {
            uint32_t ah[4][4], al[4][4];
            #pragma unroll
            for (int mt = 0; mt < 4; mt++) {
                uint32_t off = (uint32_t)(warp_m * 64 + mt * 16 + arow) * 80
                             + (uint32_t)(ks + ahalf * 8) * 2;
                ldm4(ah[mt], stg + off);
                ldm4(al[mt], stg + MTX_B + off);
            }
            uint32_t bh[4][2], bl[4][2];
            #pragma unroll
            for (int nt = 0; nt < 4; nt++) {
                uint32_t off = (uint32_t)(warp_n * 32 + nt * 8 + bnrow) * 80
                             + (uint32_t)(ks + bkh * 8) * 2;
                ldm2(bh[nt], stg + 2 * MTX_B + off);
                ldm2(bl[nt], stg + 3 * MTX_B + off);
            }
            #pragma unroll
            for (int mt = 0; mt < 4; mt++)
                #pragma unroll
                for (int nt = 0; nt < 4; nt++) {
                    mma16816(acc[mt][nt], ah[mt], bh[nt]);
                    mma16816(acc[mt][nt], ah[mt], bl[nt]);
                    mma16816(acc[mt][nt], al[mt], bh[nt]);
                }
        }
        __syncthreads();
    }

    #pragma unroll
    for (int mt = 0; mt < 4; mt++) {
        int r0 = bm + warp_m * 64 + mt * 16 + (lane >> 2);
        int r1 = r0 + 8;
        #pragma unroll
        for (int nt = 0; nt < 4; nt++) {
            int cb = bn + warp_n * 32 + nt * 8 + (lane & 3) * 2;
            float2 bs = *(const float2*)&bias[cb];
            float v0 = acc[mt][nt][0] + bs.x;
            float v1 = acc[mt][nt][1] + bs.y;
            float v2 = acc[mt][nt][2] + bs.x;
            float v3 = acc[mt][nt][3] + bs.y;
            if (EPI == 1) {
                v0 = 0.5f * v0 * (1.0f + erff(v0 * 0.70710678118654752f));
                v1 = 0.5f * v1 * (1.0f + erff(v1 * 0.70710678118654752f));
                v2 = 0.5f * v2 * (1.0f + erff(v2 * 0.70710678118654752f));
                v3 = 0.5f * v3 * (1.0f + erff(v3 * 0.70710678118654752f));
            }
            if (EPI == 1 || EPI == 3) {
                uint32_t ph0, pl0, ph1, pl1;
                packsplit2(v0, v1, ph0, pl0);
                packsplit2(v2, v3, ph1, pl1);
                *(uint32_t*)(Chi + (size_t)r0 * N + cb) = ph0;
                *(uint32_t*)(Clo + (size_t)r0 * N + cb) = pl0;
                *(uint32_t*)(Chi + (size_t)r1 * N + cb) = ph1;
                *(uint32_t*)(Clo + (size_t)r1 * N + cb) = pl1;
            } else {
                if (EPI == 2) {
                    float2 q0 = *(const float2*)&res[(size_t)r0 * N + cb];
                    float2 q1 = *(const float2*)&res[(size_t)r1 * N + cb];
                    v0 += q0.x; v1 += q0.y; v2 += q1.x; v3 += q1.y;
                }
                *(float2*)&C[(size_t)r0 * N + cb] = make_float2(v0, v1);
                *(float2*)&C[(size_t)r1 * N + cb] = make_float2(v2, v3);
            }
        }
    }
}

// ==================== Tensor-core flash attention (3xBF16 split, Br=128, Bc=64) ====================
// 8 warps; warp w owns q-rows [w*16, w*16+16). Q A-frags live in registers.
// K/V bf16 hi/lo tiles cp.async double-buffered; rows padded to 144B (conflict-free ldmatrix).
#define AT_ROWB  144
#define AT_MTXB  (64 * AT_ROWB)        // 9216
#define AT_STAGE (4 * AT_MTXB)         // 36864
#define AT_SMEM  (2 * AT_STAGE)        // 73728

__global__ __launch_bounds__(256, 1) void attn_mma(
    const bf16* __restrict__ qkvh, const bf16* __restrict__ qkvl,
    bf16* __restrict__ chi, bf16* __restrict__ clo) {
    extern __shared__ __align__(128) char smem[];
    uint32_t sb = smem_u32(smem);
    const int tid = threadIdx.x, lane = tid & 31, w = tid >> 5;
    const int qb = blockIdx.x, bh = blockIdx.y, bb = bh >> 4, h = bh & 15;
    const int tok0q = bb * LSEQ + qb * 128;

    // ---- load Q (128 x 64) hi/lo into smem stage-0 area ----
    #pragma unroll
    for (int i = 0; i < 8; i++) {
        int c = tid + i * 256;                 // 0..2047
        int mtx = c >> 10, rem = c & 1023, row = rem >> 3, q8 = rem & 7;
        const bf16* src = (mtx ? qkvl : qkvh)
                        + (size_t)(tok0q + row) * (3 * D_MODEL) + h * HDIM + q8 * 8;
        cp16(sb + mtx * 18432 + (uint32_t)row * AT_ROWB + q8 * 16, src);
    }
    cp_commit(); cp_wait<0>();
    __syncthreads();

    // ---- extract Q A-frags (kept in registers for the whole kernel) ----
    uint32_t qa[2][4][4];
    {
        int arow = lane & 15, ahf = lane >> 4;
        #pragma unroll
        for (int s = 0; s < 4; s++) {
            uint32_t off = (uint32_t)(w * 16 + arow) * AT_ROWB + (uint32_t)(s * 16 + ahf * 8) * 2;
            ldm4(qa[0][s], sb + off);
            ldm4(qa[1][s], sb + 18432 + off);
        }
    }
    __syncthreads();   // Q smem free; K/V loads may overwrite

    float accO[8][4] = {};
    float m_lo = -INFINITY, m_hi = -INFINITY, l_lo = 0.f, l_hi = 0.f;

    auto load_kv = [&](int kt) {
        uint32_t stg = sb + (uint32_t)(kt & 1) * AT_STAGE;
        int tok0 = bb * LSEQ + kt * 64;
        #pragma unroll
        for (int i = 0; i < 8; i++) {
            int c = tid + i * 256;             // 0..2047
            int mtx = c >> 9, rem = c & 511, row = rem >> 3, q8 = rem & 7;
            int col = (mtx < 2 ? D_MODEL : 2 * D_MODEL) + h * HDIM + q8 * 8;
            const bf16* src = ((mtx & 1) ? qkvl : qkvh) + (size_t)(tok0 + row) * (3 * D_MODEL) + col;
            cp16(stg + mtx * AT_MTXB + (uint32_t)row * AT_ROWB + q8 * 16, src);
        }
        cp_commit();
    };

    load_kv(0);
    const int NT = LSEQ / 64;
    for (int kt = 0; kt < NT; kt++) {
        if (kt + 1 < NT) { load_kv(kt + 1); cp_wait<1>(); }
        else             { cp_wait<0>(); }
        __syncthreads();
        uint32_t stg = sb + (uint32_t)(kt & 1) * AT_STAGE;

        // ---- S = Q @ K^T (scaled), 3-split ----
        float accS[8][4] = {};
        {
            int bnrow = lane & 7, bkh = (lane >> 3) & 1;
            #pragma unroll
            for (int nt = 0; nt < 8; nt++) {
                #pragma unroll
                for (int s = 0; s < 4; s++) {
                    uint32_t off = (uint32_t)(nt * 8 + bnrow) * AT_ROWB
                                 + (uint32_t)(s * 16 + bkh * 8) * 2;
                    uint32_t kh[2], kl[2];
                    ldm2(kh, stg + off);
                    ldm2(kl, stg + AT_MTXB + off);
                    mma16816(accS[nt], qa[0][s], kh);
                    mma16816(accS[nt], qa[0][s], kl);
                    mma16816(accS[nt], qa[1][s], kh);
                }
            }
        }
        #pragma unroll
        for (int nt = 0; nt < 8; nt++)
            #pragma unroll
            for (int j = 0; j < 4; j++) accS[nt][j] *= 0.125f;

        // ---- online softmax (rows lane>>2 and +8; quad reduction) ----
        float rmax_lo = -INFINITY, rmax_hi = -INFINITY;
        #pragma unroll
        for (int nt = 0; nt < 8; nt++) {
            rmax_lo = fmaxf(rmax_lo, fmaxf(accS[nt][0], accS[nt][1]));
            rmax_hi = fmaxf(rmax_hi, fmaxf(accS[nt][2], accS[nt][3]));
        }
        rmax_lo = fmaxf(rmax_lo, __shfl_xor_sync(0xffffffffu, rmax_lo, 1));
        rmax_lo = fmaxf(rmax_lo, __shfl_xor_sync(0xffffffffu, rmax_lo, 2));
        rmax_hi = fmaxf(rmax_hi, __shfl_xor_sync(0xffffffffu, rmax_hi, 1));
        rmax_hi = fmaxf(rmax_hi, __shfl_xor_sync(0xffffffffu, rmax_hi, 2));
        float mn_lo = fmaxf(m_lo, rmax_lo), mn_hi = fmaxf(m_hi, rmax_hi);
        float al_lo = __expf(m_lo - mn_lo), al_hi = __expf(m_hi - mn_hi);
        float rs_lo = 0.f, rs_hi = 0.f;
        #pragma unroll
        for (int nt = 0; nt < 8; nt++) {
            accS[nt][0] = __expf(accS[nt][0] - mn_lo);
            accS[nt][1] = __expf(accS[nt][1] - mn_lo);
            accS[nt][2] = __expf(accS[nt][2] - mn_hi);
            accS[nt][3] = __expf(accS[nt][3] - mn_hi);
            rs_lo += accS[nt][0] + accS[nt][1];
            rs_hi += accS[nt][2] + accS[nt][3];
        }
        rs_lo += __shfl_xor_sync(0xffffffffu, rs_lo, 1);
        rs_lo += __shfl_xor_sync(0xffffffffu, rs_lo, 2);
        rs_hi += __shfl_xor_sync(0xffffffffu, rs_hi, 1);
        rs_hi += __shfl_xor_sync(0xffffffffu, rs_hi, 2);
        l_lo = l_lo * al_lo + rs_lo; m_lo = mn_lo;
        l_hi = l_hi * al_hi + rs_hi; m_hi = mn_hi;

        #pragma unroll
        for (int nt = 0; nt < 8; nt++) {
            accO[nt][0] *= al_lo; accO[nt][1] *= al_lo;
            accO[nt][2] *= al_hi; accO[nt][3] *= al_hi;
        }

        // ---- O += P @ V  (P C-frags remapped to A-frags in registers; V via ldmatrix.trans) ----
        {
            int vrow = lane & 15, vch = (lane >> 4) << 3;
            #pragma unroll
            for (int s = 0; s < 4; s++) {
                uint32_t pah[4], pal[4];
                packsplit2(accS[2*s  ][0], accS[2*s  ][1], pah[0], pal[0]);
                packsplit2(accS[2*s  ][2], accS[2*s  ][3], pah[1], pal[1]);
                packsplit2(accS[2*s+1][0], accS[2*s+1][1], pah[2], pal[2]);
                packsplit2(accS[2*s+1][2], accS[2*s+1][3], pah[3], pal[3]);
                #pragma unroll
                for (int nt4 = 0; nt4 < 4; nt4++) {
                    uint32_t off = (uint32_t)(s * 16 + vrow) * AT_ROWB
                                 + (uint32_t)(nt4 * 16 + vch) * 2;
                    uint32_t vh[4], vl[4];
                    ldm4t(vh, stg + 2 * AT_MTXB + off);
                    ldm4t(vl, stg + 3 * AT_MTXB + off);
                    mma16816(accO[2*nt4    ], pah, vh);
                    mma16816(accO[2*nt4    ], pah, vl);
                    mma16816(accO[2*nt4    ], pal, vh);
                    mma16816(accO[2*nt4 + 1], pah, vh + 2);
                    mma16816(accO[2*nt4 + 1], pah, vl + 2);
                    mma16816(accO[2*nt4 + 1], pal, vh + 2);
                }
            }
        }
        __syncthreads();
    }

    // ---- normalize; write ctx bf16 hi/lo ----
    float inv_lo = 1.0f / l_lo, inv_hi = 1.0f / l_hi;
    int g = lane >> 2, ci = (lane & 3) * 2;
    int r0 = tok0q + w * 16 + g, r1 = r0 + 8;
    #pragma unroll
    for (int nt = 0; nt < 8; nt++) {
        int col = h * HDIM + nt * 8 + ci;
        uint32_t ph0, pl0, ph1, pl1;
        packsplit2(accO[nt][0] * inv_lo, accO[nt][1] * inv_lo, ph0, pl0);
        packsplit2(accO[nt][2] * inv_hi, accO[nt][3] * inv_hi, ph1, pl1);
        *(uint32_t*)(chi + (size_t)r0 * D_MODEL + col) = ph0;
        *(uint32_t*)(clo + (size_t)r0 * D_MODEL + col) = pl0;
        *(uint32_t*)(chi + (size_t)r1 * D_MODEL + col) = ph1;
        *(uint32_t*)(clo + (size_t)r1 * D_MODEL + col) = pl1;
    }
}

// ==================== launch ====================
extern "C" void kernel_launch(void* const* d_in, const int* in_sizes, int n_in,
                              void* d_out, int out_size) {
    (void)in_sizes; (void)n_in; (void)out_size;
    const float* x     = (const float*)d_in[0];
    const float* qkv_w = (const float*)d_in[1];
    const float* qkv_b = (const float*)d_in[2];
    const float* out_w = (const float*)d_in[3];
    const float* out_b = (const float*)d_in[4];
    const float* ff1_w = (const float*)d_in[5];
    const float* ff1_b = (const float*)d_in[6];
    const float* ff2_w = (const float*)d_in[7];
    const float* ff2_b = (const float*)d_in[8];
    const float* ln1_g = (const float*)d_in[9];
    const float* ln1_b = (const float*)d_in[10];
    const float* ln2_g = (const float*)d_in[11];
    const float* ln2_b = (const float*)d_in[12];
    float* out = (float*)d_out;

    float *x1;
    bf16 *hhi, *hlo, *qvh, *qvl, *chi, *clo, *fhi, *flo;
    bf16 *wqh, *wql, *woh, *wol, *w1h, *w1l, *w2h, *w2l;
    cudaGetSymbolAddress((void**)&x1,  g_x1);
    cudaGetSymbolAddress((void**)&hhi, g_h_hi);   cudaGetSymbolAddress((void**)&hlo, g_h_lo);
    cudaGetSymbolAddress((void**)&qvh, g_qkv_hi); cudaGetSymbolAddress((void**)&qvl, g_qkv_lo);
    cudaGetSymbolAddress((void**)&chi, g_ctx_hi); cudaGetSymbolAddress((void**)&clo, g_ctx_lo);
    cudaGetSymbolAddress((void**)&fhi, g_ff_hi);  cudaGetSymbolAddress((void**)&flo, g_ff_lo);
    cudaGetSymbolAddress((void**)&wqh, g_wqkvT_hi); cudaGetSymbolAddress((void**)&wql, g_wqkvT_lo);
    cudaGetSymbolAddress((void**)&woh, g_woutT_hi); cudaGetSymbolAddress((void**)&wol, g_woutT_lo);
    cudaGetSymbolAddress((void**)&w1h, g_wff1T_hi); cudaGetSymbolAddress((void**)&w1l, g_wff1T_lo);
    cudaGetSymbolAddress((void**)&w2h, g_wff2T_hi); cudaGetSymbolAddress((void**)&w2l, g_wff2T_lo);

    cudaFuncSetAttribute(gemm_mma<1>, cudaFuncAttributeMaxDynamicSharedMemorySize, GEMM_SMEM);
    cudaFuncSetAttribute(gemm_mma<2>, cudaFuncAttributeMaxDynamicSharedMemorySize, GEMM_SMEM);
    cudaFuncSetAttribute(gemm_mma<3>, cudaFuncAttributeMaxDynamicSharedMemorySize, GEMM_SMEM);
    cudaFuncSetAttribute(attn_mma,    cudaFuncAttributeMaxDynamicSharedMemorySize, AT_SMEM);

    dim3 tb(32, 8);
    wconv<<<dim3(3 * D_MODEL / 32, D_MODEL / 32), tb>>>(qkv_w, D_MODEL, 3 * D_MODEL, wqh, wql);
    wconv<<<dim3(D_MODEL / 32, D_MODEL / 32), tb>>>(out_w, D_MODEL, D_MODEL, woh, wol);
    wconv<<<dim3(FFH / 32, D_MODEL / 32), tb>>>(ff1_w, D_MODEL, FFH, w1h, w1l);
    wconv<<<dim3(D_MODEL / 32, FFH / 32), tb>>>(ff2_w, FFH, D_MODEL, w2h, w2l);

    // 1) h = LN1(x)
    ln_kernel<<<NTOK, 256>>>(x, ln1_g, ln1_b, hhi, hlo);
    // 2) qkv = h @ qkv_w + b  -> bf16 hi/lo
    gemm_mma<3><<<dim3(3 * D_MODEL / 128, NTOK / 128), 256, GEMM_SMEM>>>(
        D_MODEL, 3 * D_MODEL, hhi, hlo, wqh, wql, qkv_b, nullptr, nullptr, qvh, qvl);
    // 3) ctx = attention(qkv) -> bf16 hi/lo
    attn_mma<<<dim3(LSEQ / 128, 4 * NHEAD), 256, AT_SMEM>>>(qvh, qvl, chi, clo);
    // 4) x1 = x + ctx @ out_w + b
    gemm_mma<2><<<dim3(D_MODEL / 128, NTOK / 128), 256, GEMM_SMEM>>>(
        D_MODEL, D_MODEL, chi, clo, woh, wol, out_b, x, x1, nullptr, nullptr);
    // 5) h = LN2(x1)
    ln_kernel<<<NTOK, 256>>>(x1, ln2_g, ln2_b, hhi, hlo);
    // 6) ff = gelu(h @ ff1_w + b) -> bf16 hi/lo
    gemm_mma<1><<<dim3(FFH / 128, NTOK / 128), 256, GEMM_SMEM>>>(
        D_MODEL, FFH, hhi, hlo, w1h, w1l, ff1_b, nullptr, nullptr, fhi, flo);
    // 7) out = x1 + ff @ ff2_w + b
    gemm_mma<2><<<dim3(D_MODEL / 128, NTOK / 128), 256, GEMM_SMEM>>>(
        FFH, D_MODEL, fhi, flo, w2h, w2l, ff2_b, x1, out, nullptr, nullptr);
}